// round 12
// baseline (speedup 1.0000x reference)
#include <cuda_runtime.h>
#include <cuda_bf16.h>
#include <cstdint>

#define F 26
#define D 128
#define NROWS 100000
#define B 4096
#define T (B * 20)

// ---- per-warp register gather ---------------------------------------------
// Lane l owns the l-th float4 (16B) of each 512B row. Direct LDG.128 gathers
// with 4 independent accumulators (MLP=4). No smem round-trip: halves L1tex
// wavefronts per row vs the cp.async+LDS pipeline.
__device__ __forceinline__ float4 gather_accum(
    const int* __restrict__ vals, int lo, int hi,
    const float4* __restrict__ tab, int lane)
{
    float4 a0 = make_float4(0.f, 0.f, 0.f, 0.f);
    float4 a1 = make_float4(0.f, 0.f, 0.f, 0.f);
    float4 a2 = make_float4(0.f, 0.f, 0.f, 0.f);
    float4 a3 = make_float4(0.f, 0.f, 0.f, 0.f);

    for (int base = lo; base < hi; base += 32) {
        const int n = min(32, hi - base);
        int myidx = 0;
        if (base + lane < hi) myidx = __ldg(vals + base + lane);

        int j = 0;
        for (; j + 4 <= n; j += 4) {
            int r0 = __shfl_sync(0xffffffffu, myidx, j + 0);
            int r1 = __shfl_sync(0xffffffffu, myidx, j + 1);
            int r2 = __shfl_sync(0xffffffffu, myidx, j + 2);
            int r3 = __shfl_sync(0xffffffffu, myidx, j + 3);
            float4 v0 = __ldg(tab + (size_t)(unsigned)r0 * 32 + lane);
            float4 v1 = __ldg(tab + (size_t)(unsigned)r1 * 32 + lane);
            float4 v2 = __ldg(tab + (size_t)(unsigned)r2 * 32 + lane);
            float4 v3 = __ldg(tab + (size_t)(unsigned)r3 * 32 + lane);
            a0.x += v0.x; a0.y += v0.y; a0.z += v0.z; a0.w += v0.w;
            a1.x += v1.x; a1.y += v1.y; a1.z += v1.z; a1.w += v1.w;
            a2.x += v2.x; a2.y += v2.y; a2.z += v2.z; a2.w += v2.w;
            a3.x += v3.x; a3.y += v3.y; a3.z += v3.z; a3.w += v3.w;
        }
        for (; j < n; ++j) {
            int r0 = __shfl_sync(0xffffffffu, myidx, j);
            float4 v0 = __ldg(tab + (size_t)(unsigned)r0 * 32 + lane);
            a0.x += v0.x; a0.y += v0.y; a0.z += v0.z; a0.w += v0.w;
        }
    }

    float4 acc;
    acc.x = (a0.x + a1.x) + (a2.x + a3.x);
    acc.y = (a0.y + a1.y) + (a2.y + a3.y);
    acc.z = (a0.z + a1.z) + (a2.z + a3.z);
    acc.w = (a0.w + a1.w) + (a2.w + a3.w);
    return acc;
}

// ---- fused, sum-split kernel ----------------------------------------------
// Block = 8 warps = 8 consecutive bags of one feature. Offsets are cumulative,
// so the 8 bags occupy ONE contiguous range of vals, split EVENLY over the 8
// warps (crossing bag boundaries) -> zero intra-block imbalance. Per-bag
// partials combine via smem atomicAdd; warp w writes bag w.
__global__ __launch_bounds__(256, 5) void ebag_fused(
    const float* __restrict__ tables,   // [F, NROWS, D]
    const int* __restrict__ values,     // [F, T]
    const int* __restrict__ offsets,    // [F, B+1]
    float* __restrict__ out)            // [B, F, D]
{
    __shared__ __align__(16) float part[8][128]; // 4KB: per-bag partial sums

    const int lane = threadIdx.x & 31;
    const int warp = threadIdx.x >> 5;
    const int f    = blockIdx.y;
    const int bag0 = blockIdx.x * 8;

    const int* offs = offsets + f * (B + 1);
    // 9 boundary offsets held warp-wide in one register, fetched via shfl.
    int off_l = 0;
    if (lane < 9) off_l = __ldg(offs + bag0 + lane);

    // zero the partial buffer (256 threads x 4 floats = 1024 floats)
    reinterpret_cast<float4*>(&part[0][0])[threadIdx.x] =
        make_float4(0.f, 0.f, 0.f, 0.f);
    __syncthreads();

    const int S = __shfl_sync(0xffffffffu, off_l, 0);
    const int E = __shfl_sync(0xffffffffu, off_l, 8);
    const int total = E - S;

    const int* vals = values + (size_t)f * T;
    const float4* tab = reinterpret_cast<const float4*>(
        tables + (size_t)f * NROWS * D);

    // this warp's even share of the concatenated range
    int lo = S + (int)(((long long)total * warp) >> 3);
    int hi = S + (int)(((long long)total * (warp + 1)) >> 3);

    if (lo < hi) {
        // find first bag j containing lo: largest j with offs[j] <= lo
        int j = 0;
        int oj1 = __shfl_sync(0xffffffffu, off_l, 1);
        while (j < 7) {
            if (oj1 > lo) break;
            ++j;
            oj1 = __shfl_sync(0xffffffffu, off_l, j + 1);
        }

        int p = lo;
        while (p < hi) {
            const int ce = min(hi, oj1);        // chunk end within bag j
            if (ce > p) {
                float4 acc = gather_accum(vals, p, ce, tab, lane);
                float* pj = &part[j][lane * 4];
                atomicAdd(pj + 0, acc.x);
                atomicAdd(pj + 1, acc.y);
                atomicAdd(pj + 2, acc.z);
                atomicAdd(pj + 3, acc.w);
                p = ce;
            }
            if (p >= hi) break;
            ++j;
            oj1 = __shfl_sync(0xffffffffu, off_l, j + 1);
        }
    }
    __syncthreads();

    // warp w writes bag w (always: empty bags must be 0, d_out is poisoned)
    float4 res = reinterpret_cast<const float4*>(&part[warp][0])[lane];
    float4* o = reinterpret_cast<float4*>(out) + ((size_t)(bag0 + warp) * F + f) * 32;
    o[lane] = res;
}

extern "C" void kernel_launch(void* const* d_in, const int* in_sizes, int n_in,
                              void* d_out, int out_size) {
    const float* tables  = (const float*)d_in[0];
    const int*   values  = (const int*)d_in[1];
    const int*   offsets = (const int*)d_in[2];
    float* out = (float*)d_out;

    dim3 grid(B / 8, F);   // feature on y: blocks of one feature grouped -> L2 reuse
    dim3 block(256);       // 8 warps, 8 bags, sum-split evenly
    ebag_fused<<<grid, block>>>(tables, values, offsets, out);
}

// round 13
// speedup vs baseline: 1.1000x; 1.1000x over previous
#include <cuda_runtime.h>
#include <cuda_bf16.h>
#include <cstdint>

#define F 26
#define D 128
#define NROWS 100000
#define B 4096
#define T (B * 20)

// Block = 8 warps = 8 consecutive bags of one feature (sum-split: the bags'
// concatenated index range is divided EVENLY over the 8 warps, crossing bag
// boundaries -> zero intra-block imbalance).
// Row gathers: ONE cp.async.bulk (512B, TMA engine) per row, issued by lane 0,
// completion via mbarrier. Data bypasses per-lane L1tex wavefronts on the way
// in; only the LDS.128 readback touches L1. Double-buffered stages of 4 rows.
__global__ __launch_bounds__(256, 6) void ebag_fused(
    const float* __restrict__ tables,   // [F, NROWS, D]
    const int* __restrict__ values,     // [F, T]
    const int* __restrict__ offsets,    // [F, B+1]
    float* __restrict__ out)            // [B, F, D]
{
    __shared__ float4 buf[8][8][32];              // 32KB: per-warp ring (8 rows)
    __shared__ __align__(16) float part[8][128];  // 4KB: per-bag partial sums
    __shared__ __align__(8) unsigned long long mbar[8][2]; // 2 mbarriers/warp

    const int lane = threadIdx.x & 31;
    const int warp = threadIdx.x >> 5;
    const int f    = blockIdx.y;
    const int bag0 = blockIdx.x * 8;

    // init mbarriers + zero partials
    if (lane == 0) {
        uint32_t m0 = (uint32_t)__cvta_generic_to_shared(&mbar[warp][0]);
        uint32_t m1 = (uint32_t)__cvta_generic_to_shared(&mbar[warp][1]);
        asm volatile("mbarrier.init.shared.b64 [%0], 1;" :: "r"(m0) : "memory");
        asm volatile("mbarrier.init.shared.b64 [%0], 1;" :: "r"(m1) : "memory");
    }
    reinterpret_cast<float4*>(&part[0][0])[threadIdx.x] =
        make_float4(0.f, 0.f, 0.f, 0.f);
    asm volatile("fence.proxy.async.shared::cta;" ::: "memory");
    __syncthreads();

    const int* offs = offsets + f * (B + 1);
    int off_l = 0;
    if (lane < 9) off_l = __ldg(offs + bag0 + lane);

    const int S = __shfl_sync(0xffffffffu, off_l, 0);
    const int E = __shfl_sync(0xffffffffu, off_l, 8);
    const int total = E - S;

    const int* vals = values + (size_t)f * T;
    const char* tabb = reinterpret_cast<const char*>(
        tables + (size_t)f * NROWS * D);

    const uint32_t ring0 = (uint32_t)__cvta_generic_to_shared(&buf[warp][0][0]);
    const uint32_t mb[2] = {
        (uint32_t)__cvta_generic_to_shared(&mbar[warp][0]),
        (uint32_t)__cvta_generic_to_shared(&mbar[warp][1]) };

    // this warp's even share of the concatenated range
    const int lo = S + (int)(((long long)total * warp) >> 3);
    const int hi = S + (int)(((long long)total * (warp + 1)) >> 3);

    if (lo < hi) {
        // consume-side bag tracking: first bag j containing lo
        int j = 0;
        int oj1 = __shfl_sync(0xffffffffu, off_l, 1);
        while (j < 7 && oj1 <= lo) {
            ++j;
            oj1 = __shfl_sync(0xffffffffu, off_l, j + 1);
        }

        float4 acc = make_float4(0.f, 0.f, 0.f, 0.f);
        const int nrows  = hi - lo;
        const int nstage = (nrows + 3) >> 2;
        unsigned ph0 = 0, ph1 = 0;        // mbarrier phases
        int myidx = 0;

        for (int st = 0; st < nstage; ++st) {
            // refresh the 32-wide coalesced index block every 8 stages
            if ((st & 7) == 0) {
                const int base = lo + (st << 2);
                myidx = (base + lane < hi) ? __ldg(vals + base + lane) : 0;
            }
            const int cnt = min(4, nrows - (st << 2));
            const int sid = st & 1;

            // broadcast this stage's row ids (collective shfl, lane0 uses them)
            const int sl = (st & 7) << 2;
            int r0 = __shfl_sync(0xffffffffu, myidx, sl + 0);
            int r1 = __shfl_sync(0xffffffffu, myidx, sl + 1);
            int r2 = __shfl_sync(0xffffffffu, myidx, sl + 2);
            int r3 = __shfl_sync(0xffffffffu, myidx, sl + 3);

            if (lane == 0) {
                asm volatile("mbarrier.arrive.expect_tx.shared.b64 _, [%0], %1;"
                             :: "r"(mb[sid]), "r"(cnt * 512) : "memory");
                const int rr[4] = {r0, r1, r2, r3};
                #pragma unroll
                for (int q = 0; q < 4; ++q) {
                    if (q < cnt) {
                        const char* src = tabb + ((size_t)(unsigned)rr[q] << 9);
                        uint32_t dst = ring0 + (uint32_t)(((sid << 2) + q) << 9);
                        asm volatile(
                            "cp.async.bulk.shared::cta.global.mbarrier::complete_tx::bytes "
                            "[%0], [%1], 512, [%2];"
                            :: "r"(dst), "l"(src), "r"(mb[sid]) : "memory");
                    }
                }
            }

            // consume stage st-1 while stage st is in flight
            if (st > 0) {
                const int ps  = st - 1;
                const int psid = ps & 1;
                unsigned phase = psid ? ph1 : ph0;
                unsigned done;
                asm volatile(
                    "{\n\t.reg .pred p;\n\t"
                    "mbarrier.try_wait.parity.shared.b64 p, [%1], %2;\n\t"
                    "selp.b32 %0, 1, 0, p;\n\t}"
                    : "=r"(done) : "r"(mb[psid]), "r"(phase) : "memory");
                while (!done) {
                    asm volatile(
                        "{\n\t.reg .pred p;\n\t"
                        "mbarrier.try_wait.parity.shared.b64 p, [%1], %2;\n\t"
                        "selp.b32 %0, 1, 0, p;\n\t}"
                        : "=r"(done) : "r"(mb[psid]), "r"(phase) : "memory");
                }
                if (psid) ph1 ^= 1; else ph0 ^= 1;

                const int pcnt = min(4, nrows - (ps << 2));
                #pragma unroll
                for (int q = 0; q < 4; ++q) {
                    if (q < pcnt) {
                        const int pos = lo + (ps << 2) + q;
                        if (pos >= oj1) {     // bag boundary: flush partial
                            float* pj = &part[j][lane * 4];
                            atomicAdd(pj + 0, acc.x);
                            atomicAdd(pj + 1, acc.y);
                            atomicAdd(pj + 2, acc.z);
                            atomicAdd(pj + 3, acc.w);
                            acc = make_float4(0.f, 0.f, 0.f, 0.f);
                            while (j < 7 && oj1 <= pos) {
                                ++j;
                                oj1 = __shfl_sync(0xffffffffu, off_l, j + 1);
                            }
                        }
                        float4 v = buf[warp][(psid << 2) + q][lane];
                        acc.x += v.x; acc.y += v.y; acc.z += v.z; acc.w += v.w;
                    }
                }
            }
            __syncwarp();   // all lanes done with slot before it is re-filled
        }

        // drain last stage
        {
            const int ps  = nstage - 1;
            const int psid = ps & 1;
            unsigned phase = psid ? ph1 : ph0;
            unsigned done;
            do {
                asm volatile(
                    "{\n\t.reg .pred p;\n\t"
                    "mbarrier.try_wait.parity.shared.b64 p, [%1], %2;\n\t"
                    "selp.b32 %0, 1, 0, p;\n\t}"
                    : "=r"(done) : "r"(mb[psid]), "r"(phase) : "memory");
            } while (!done);

            const int pcnt = min(4, nrows - (ps << 2));
            #pragma unroll
            for (int q = 0; q < 4; ++q) {
                if (q < pcnt) {
                    const int pos = lo + (ps << 2) + q;
                    if (pos >= oj1) {
                        float* pj = &part[j][lane * 4];
                        atomicAdd(pj + 0, acc.x);
                        atomicAdd(pj + 1, acc.y);
                        atomicAdd(pj + 2, acc.z);
                        atomicAdd(pj + 3, acc.w);
                        acc = make_float4(0.f, 0.f, 0.f, 0.f);
                        while (j < 7 && oj1 <= pos) {
                            ++j;
                            oj1 = __shfl_sync(0xffffffffu, off_l, j + 1);
                        }
                    }
                    float4 v = buf[warp][(psid << 2) + q][lane];
                    acc.x += v.x; acc.y += v.y; acc.z += v.z; acc.w += v.w;
                }
            }
        }

        // final flush
        float* pj = &part[j][lane * 4];
        atomicAdd(pj + 0, acc.x);
        atomicAdd(pj + 1, acc.y);
        atomicAdd(pj + 2, acc.z);
        atomicAdd(pj + 3, acc.w);
    }
    __syncthreads();

    // warp w writes bag w (always: empty bags must be 0, d_out is poisoned)
    float4 res = reinterpret_cast<const float4*>(&part[warp][0])[lane];
    float4* o = reinterpret_cast<float4*>(out) + ((size_t)(bag0 + warp) * F + f) * 32;
    o[lane] = res;
}

extern "C" void kernel_launch(void* const* d_in, const int* in_sizes, int n_in,
                              void* d_out, int out_size) {
    const float* tables  = (const float*)d_in[0];
    const int*   values  = (const int*)d_in[1];
    const int*   offsets = (const int*)d_in[2];
    float* out = (float*)d_out;

    dim3 grid(B / 8, F);   // feature on y: blocks of one feature grouped -> L2 reuse
    dim3 block(256);       // 8 warps, 8 bags, sum-split evenly
    ebag_fused<<<grid, block>>>(tables, values, offsets, out);
}